// round 14
// baseline (speedup 1.0000x reference)
#include <cuda_runtime.h>
#include <cuda_fp16.h>
#include <mma.h>
#include <cstddef>

using namespace nvcuda;

#define NN      100000
#define EE      1200000
#define NFEAT_K 128
#define NHID    64
#define NCLASS  16
#define NN_PAD  100096   // NN rounded up to 128 (wmma stores unguarded per tile)
#define SCAN_BLOCKS 196  // ceil(NN / 512)

// ---- scratch (__device__ globals; no runtime allocation allowed) ----------
__device__ __half g_h0h [(size_t)NN * NHID];      // h0 = x@fc0_w + fc0_b, fp16
__device__ __half g_xwhA[(size_t)NN_PAD * NHID];  // gemm outputs, ping
__device__ __half g_xwhB[(size_t)NN_PAD * NHID];  // gemm outputs, pong
// CSR (built once per launch; adjacency identical across the 4 layers)
__device__ int      g_cnt  [NN];      // zero at entry (zero-init + re-zeroed by scan)
__device__ unsigned g_state[256];     // lookback state; zeroed by k_hist blk 0
__device__ int      g_rptr [NN + 1];
__device__ int      g_cursor[NN];
__device__ __align__(16) int2 g_ev[EE];           // (col, __float_as_int(0.9*val))

// ---------------------------------------------------------------------------
// SpMM row helper: acc(lane) = 0.1*h0h[r] + cb + sum_e 0.9*val*xwh[col_e]
// (one warp per row, lane owns a half2 -> fully-coalesced 128B gather/edge;
// unroll x8 via int4 ev loads, parity peel for 16B alignment; fp32 accum)
// ---------------------------------------------------------------------------
__device__ __forceinline__ float2 spmm_row(
    int r, int lane, const int* __restrict__ rptr, const int2* __restrict__ ev,
    const __half2* __restrict__ xwh, const __half2* __restrict__ h0h,
    float2 c)
{
    int start = __ldg(rptr + r);
    int end   = __ldg(rptr + r + 1);

    float2 h = __half22float2(__ldg(h0h + (size_t)r * (NHID / 2) + lane));
    float2 acc = make_float2(fmaf(0.1f, h.x, c.x), fmaf(0.1f, h.y, c.y));

    int e = start;
    if ((e & 1) && e < end) {
        int2 e0 = __ldg(ev + e);
        float2 f0 = __half22float2(__ldg(xwh + (size_t)e0.x * (NHID / 2) + lane));
        float v0 = __int_as_float(e0.y);
        acc.x = fmaf(v0, f0.x, acc.x);
        acc.y = fmaf(v0, f0.y, acc.y);
        e++;
    }
    for (; e + 7 < end; e += 8) {
        int4 q0 = __ldg((const int4*)(ev + e) + 0);
        int4 q1 = __ldg((const int4*)(ev + e) + 1);
        int4 q2 = __ldg((const int4*)(ev + e) + 2);
        int4 q3 = __ldg((const int4*)(ev + e) + 3);
        __half2 x0 = __ldg(xwh + (size_t)q0.x * (NHID / 2) + lane);
        __half2 x1 = __ldg(xwh + (size_t)q0.z * (NHID / 2) + lane);
        __half2 x2 = __ldg(xwh + (size_t)q1.x * (NHID / 2) + lane);
        __half2 x3 = __ldg(xwh + (size_t)q1.z * (NHID / 2) + lane);
        __half2 x4 = __ldg(xwh + (size_t)q2.x * (NHID / 2) + lane);
        __half2 x5 = __ldg(xwh + (size_t)q2.z * (NHID / 2) + lane);
        __half2 x6 = __ldg(xwh + (size_t)q3.x * (NHID / 2) + lane);
        __half2 x7 = __ldg(xwh + (size_t)q3.z * (NHID / 2) + lane);
        float2 f0 = __half22float2(x0), f1 = __half22float2(x1);
        float2 f2 = __half22float2(x2), f3 = __half22float2(x3);
        float2 f4 = __half22float2(x4), f5 = __half22float2(x5);
        float2 f6 = __half22float2(x6), f7 = __half22float2(x7);
        float v0 = __int_as_float(q0.y), v1 = __int_as_float(q0.w);
        float v2 = __int_as_float(q1.y), v3 = __int_as_float(q1.w);
        float v4 = __int_as_float(q2.y), v5 = __int_as_float(q2.w);
        float v6 = __int_as_float(q3.y), v7 = __int_as_float(q3.w);
        acc.x = fmaf(v0, f0.x, acc.x);  acc.y = fmaf(v0, f0.y, acc.y);
        acc.x = fmaf(v1, f1.x, acc.x);  acc.y = fmaf(v1, f1.y, acc.y);
        acc.x = fmaf(v2, f2.x, acc.x);  acc.y = fmaf(v2, f2.y, acc.y);
        acc.x = fmaf(v3, f3.x, acc.x);  acc.y = fmaf(v3, f3.y, acc.y);
        acc.x = fmaf(v4, f4.x, acc.x);  acc.y = fmaf(v4, f4.y, acc.y);
        acc.x = fmaf(v5, f5.x, acc.x);  acc.y = fmaf(v5, f5.y, acc.y);
        acc.x = fmaf(v6, f6.x, acc.x);  acc.y = fmaf(v6, f6.y, acc.y);
        acc.x = fmaf(v7, f7.x, acc.x);  acc.y = fmaf(v7, f7.y, acc.y);
    }
    for (; e + 1 < end; e += 2) {
        int4 q = __ldg((const int4*)(ev + e));
        __half2 x0 = __ldg(xwh + (size_t)q.x * (NHID / 2) + lane);
        __half2 x1 = __ldg(xwh + (size_t)q.z * (NHID / 2) + lane);
        float2 f0 = __half22float2(x0), f1 = __half22float2(x1);
        float v0 = __int_as_float(q.y), v1 = __int_as_float(q.w);
        acc.x = fmaf(v0, f0.x, acc.x);  acc.y = fmaf(v0, f0.y, acc.y);
        acc.x = fmaf(v1, f1.x, acc.x);  acc.y = fmaf(v1, f1.y, acc.y);
    }
    if (e < end) {
        int2 e0 = __ldg(ev + e);
        float2 f0 = __half22float2(__ldg(xwh + (size_t)e0.x * (NHID / 2) + lane));
        float v0 = __int_as_float(e0.y);
        acc.x = fmaf(v0, f0.x, acc.x);
        acc.y = fmaf(v0, f0.y, acc.y);
    }
    return acc;
}

// ---------------------------------------------------------------------------
// FUSED layer kernel: block owns rows [row0, row0+128).
//   phase 1 (spmm): li[r] = 0.1*h0+cb + 0.9*A@xwh_in, relu+fp16 into smem As
//   phase 2 (gemm): xwh_out[rows] = fp16( As @ W[64,64] )  via wmma
// li never touches gmem. Identical rounding to the unfused pipeline.
// ---------------------------------------------------------------------------
__global__ __launch_bounds__(256)
void layer_fused(const int* __restrict__ rptr, const int2* __restrict__ ev,
                 const __half2* __restrict__ xwh_in,
                 const __half2* __restrict__ h0h, const float* __restrict__ cb,
                 const float* __restrict__ W, __half* __restrict__ xwh_out)
{
    constexpr int LDA = 72;
    __shared__ __half As[128 * LDA];
    __shared__ __half Bs[64 * LDA];

    const int t    = threadIdx.x;
    const int warp = t >> 5;
    const int lane = t & 31;
    const int row0 = blockIdx.x * 128;

    // Stage W[64][64] fp32 -> fp16 smem (done before spmm; no dependence)
#pragma unroll
    for (int i = t; i < 64 * 16; i += 256) {
        int r  = i >> 4;
        int c4 = i & 15;
        float4 v = __ldg((const float4*)(W + (size_t)r * 64) + c4);
        __half2* dst = (__half2*)(Bs + r * LDA + c4 * 4);
        dst[0] = __floats2half2_rn(v.x, v.y);
        dst[1] = __floats2half2_rn(v.z, v.w);
    }

    float2 c = __ldg((const float2*)cb + lane);

    // Phase 1: spmm rows (warp strides over 16 rows)
    for (int rr = warp; rr < 128; rr += 8) {
        int r = row0 + rr;
        float2 acc = make_float2(0.f, 0.f);
        if (r < NN) acc = spmm_row(r, lane, rptr, ev, xwh_in, h0h, c);
        // relu + fp16 into the wmma A tile
        *(__half2*)(As + rr * LDA + lane * 2) =
            __floats2half2_rn(fmaxf(acc.x, 0.f), fmaxf(acc.y, 0.f));
    }
    __syncthreads();

    // Phase 2: wmma 128x64x64 (8 warps, 4Mx2N, warp tile 32x32)
    const int wm = warp & 3;
    const int wn = warp >> 2;

    wmma::fragment<wmma::accumulator, 16, 16, 16, float> cf[2][2];
#pragma unroll
    for (int i = 0; i < 2; i++)
#pragma unroll
        for (int j = 0; j < 2; j++) wmma::fill_fragment(cf[i][j], 0.f);

#pragma unroll
    for (int k = 0; k < 64; k += 16) {
        wmma::fragment<wmma::matrix_a, 16, 16, 16, __half, wmma::row_major> a0, a1;
        wmma::fragment<wmma::matrix_b, 16, 16, 16, __half, wmma::row_major> b0, b1;
        wmma::load_matrix_sync(a0, As + (wm * 32 +  0) * LDA + k, LDA);
        wmma::load_matrix_sync(a1, As + (wm * 32 + 16) * LDA + k, LDA);
        wmma::load_matrix_sync(b0, Bs + k * LDA + wn * 32 +  0, LDA);
        wmma::load_matrix_sync(b1, Bs + k * LDA + wn * 32 + 16, LDA);
        wmma::mma_sync(cf[0][0], a0, b0, cf[0][0]);
        wmma::mma_sync(cf[0][1], a0, b1, cf[0][1]);
        wmma::mma_sync(cf[1][0], a1, b0, cf[1][0]);
        wmma::mma_sync(cf[1][1], a1, b1, cf[1][1]);
    }

#pragma unroll
    for (int i = 0; i < 2; i++)
#pragma unroll
        for (int j = 0; j < 2; j++) {
            wmma::fragment<wmma::accumulator, 16, 16, 16, __half> hc;
#pragma unroll
            for (int e = 0; e < hc.num_elements; e++)
                hc.x[e] = __float2half(cf[i][j].x[e]);
            __half* dst = xwh_out + (size_t)(row0 + wm * 32 + i * 16) * 64
                                  + wn * 32 + j * 16;
            wmma::store_matrix_sync(dst, hc, 64, wmma::mem_row_major);
        }
}

// ---------------------------------------------------------------------------
// FUSED last layer: spmm_3 -> relu -> fc1 (64->16) -> d_out (fp32)
// ---------------------------------------------------------------------------
__global__ __launch_bounds__(256)
void layer_last_fused(const int* __restrict__ rptr, const int2* __restrict__ ev,
                      const __half2* __restrict__ xwh_in,
                      const __half2* __restrict__ h0h, const float* __restrict__ cb,
                      const float* __restrict__ fw, const float* __restrict__ fb,
                      float* __restrict__ out)
{
    constexpr int LDA = 72;
    __shared__ __half As[128 * LDA];
    __shared__ float  Wf[NHID * NCLASS];
    __shared__ float  bf[NCLASS];

    const int t    = threadIdx.x;
    const int warp = t >> 5;
    const int lane = t & 31;
    const int row0 = blockIdx.x * 128;

    for (int i = t; i < NHID * NCLASS; i += 256) Wf[i] = __ldg(fw + i);
    if (t < NCLASS) bf[t] = __ldg(fb + t);

    float2 c = __ldg((const float2*)cb + lane);

    for (int rr = warp; rr < 128; rr += 8) {
        int r = row0 + rr;
        float2 acc = make_float2(0.f, 0.f);
        if (r < NN) acc = spmm_row(r, lane, rptr, ev, xwh_in, h0h, c);
        *(__half2*)(As + rr * LDA + lane * 2) =
            __floats2half2_rn(fmaxf(acc.x, 0.f), fmaxf(acc.y, 0.f));
    }
    __syncthreads();

    // fc1: thread t handles row rr = t>>1, cols [8*(t&1), 8*(t&1)+8)
    int rr = t >> 1;
    int j8 = (t & 1) * 8;
    int row = row0 + rr;
    if (row >= NN) return;

    float acc[8];
#pragma unroll
    for (int n = 0; n < 8; n++) acc[n] = bf[j8 + n];

#pragma unroll 8
    for (int k = 0; k < NHID; k++) {
        float xv = __half2float(As[rr * LDA + k]);   // relu already applied
        const float* wr = Wf + k * NCLASS + j8;
#pragma unroll
        for (int n = 0; n < 8; n++) acc[n] = fmaf(xv, wr[n], acc[n]);
    }

    float4* o = (float4*)(out + (size_t)row * NCLASS + j8);
    o[0] = make_float4(acc[0], acc[1], acc[2], acc[3]);
    o[1] = make_float4(acc[4], acc[5], acc[6], acc[7]);
}

// ---------------------------------------------------------------------------
// Dense-branch kernels (fork): fc0 fp32->fp16, then conv GEMM layer 0 (wmma).
// ---------------------------------------------------------------------------
__global__ __launch_bounds__(256)
void conv_gemm_wmma(const __half* __restrict__ in, const float* __restrict__ W,
                    __half* __restrict__ out)
{
    constexpr int LDA = 72;
    __shared__ __half As[128 * LDA];
    __shared__ __half Bs[64 * LDA];

    const int t    = threadIdx.x;
    const int row0 = blockIdx.x * 128;

#pragma unroll
    for (int i = t; i < 128 * 16; i += 256) {
        int r  = i >> 4;
        int c4 = i & 15;
        int row = row0 + r;
        uint2 u = make_uint2(0u, 0u);
        if (row < NN) u = __ldg((const uint2*)(in + (size_t)row * NHID) + c4);
        __half2 z = __float2half2_rn(0.f);
        __half2* dst = (__half2*)(As + r * LDA + c4 * 4);
        dst[0] = __hmax2(*(__half2*)&u.x, z);
        dst[1] = __hmax2(*(__half2*)&u.y, z);
    }
#pragma unroll
    for (int i = t; i < 64 * 16; i += 256) {
        int r  = i >> 4;
        int c4 = i & 15;
        float4 v = __ldg((const float4*)(W + (size_t)r * 64) + c4);
        __half2* dst = (__half2*)(Bs + r * LDA + c4 * 4);
        dst[0] = __floats2half2_rn(v.x, v.y);
        dst[1] = __floats2half2_rn(v.z, v.w);
    }
    __syncthreads();

    const int wid = t >> 5;
    const int wm  = wid & 3;
    const int wn  = wid >> 2;

    wmma::fragment<wmma::accumulator, 16, 16, 16, float> c[2][2];
#pragma unroll
    for (int i = 0; i < 2; i++)
#pragma unroll
        for (int j = 0; j < 2; j++) wmma::fill_fragment(c[i][j], 0.f);

#pragma unroll
    for (int k = 0; k < 64; k += 16) {
        wmma::fragment<wmma::matrix_a, 16, 16, 16, __half, wmma::row_major> a0, a1;
        wmma::fragment<wmma::matrix_b, 16, 16, 16, __half, wmma::row_major> b0, b1;
        wmma::load_matrix_sync(a0, As + (wm * 32 +  0) * LDA + k, LDA);
        wmma::load_matrix_sync(a1, As + (wm * 32 + 16) * LDA + k, LDA);
        wmma::load_matrix_sync(b0, Bs + k * LDA + wn * 32 +  0, LDA);
        wmma::load_matrix_sync(b1, Bs + k * LDA + wn * 32 + 16, LDA);
        wmma::mma_sync(c[0][0], a0, b0, c[0][0]);
        wmma::mma_sync(c[0][1], a0, b1, c[0][1]);
        wmma::mma_sync(c[1][0], a1, b0, c[1][0]);
        wmma::mma_sync(c[1][1], a1, b1, c[1][1]);
    }

#pragma unroll
    for (int i = 0; i < 2; i++)
#pragma unroll
        for (int j = 0; j < 2; j++) {
            wmma::fragment<wmma::accumulator, 16, 16, 16, __half> hc;
#pragma unroll
            for (int e = 0; e < hc.num_elements; e++)
                hc.x[e] = __float2half(c[i][j].x[e]);
            __half* dst = out + (size_t)(row0 + wm * 32 + i * 16) * 64
                              + wn * 32 + j * 16;
            wmma::store_matrix_sync(dst, hc, 64, wmma::mem_row_major);
        }
}

template<int K>
__global__ __launch_bounds__(256)
void tile_gemm_f32h(const float* __restrict__ in, const float* __restrict__ W,
                    const float* __restrict__ b, __half* __restrict__ out)
{
    constexpr int BM = 128, BN = 64, BK = 64;
    __shared__ float4 xs4[BM][BK / 4];
    __shared__ float4 ws4[BK][BN / 4];

    const int t    = threadIdx.x;
    const int ng   = t & 15;
    const int mg   = t >> 4;
    const int row0 = blockIdx.x * BM;

    float4 acc[8];
#pragma unroll
    for (int r = 0; r < 8; r++) acc[r] = make_float4(0.f, 0.f, 0.f, 0.f);

    for (int kt = 0; kt < K; kt += BK) {
        {
            const float4* Wg = (const float4*)(W + (size_t)kt * BN);
#pragma unroll
            for (int i = t; i < BK * BN / 4; i += 256)
                ws4[i >> 4][i & 15] = __ldg(Wg + i);
        }
#pragma unroll
        for (int i = t; i < BM * BK / 4; i += 256) {
            int r  = i >> 4;
            int k4 = i & 15;
            int row = row0 + r;
            float4 v = make_float4(0.f, 0.f, 0.f, 0.f);
            if (row < NN) v = __ldg((const float4*)(in + (size_t)row * K + kt) + k4);
            xs4[r][k4] = v;
        }
        __syncthreads();

#pragma unroll 4
        for (int k4 = 0; k4 < BK / 4; k4++) {
            float4 w0 = ws4[k4 * 4 + 0][ng];
            float4 w1 = ws4[k4 * 4 + 1][ng];
            float4 w2 = ws4[k4 * 4 + 2][ng];
            float4 w3 = ws4[k4 * 4 + 3][ng];
#pragma unroll
            for (int r = 0; r < 8; r++) {
                float4 xv = xs4[mg * 8 + r][k4];
                acc[r].x = fmaf(xv.x, w0.x, acc[r].x);
                acc[r].y = fmaf(xv.x, w0.y, acc[r].y);
                acc[r].z = fmaf(xv.x, w0.z, acc[r].z);
                acc[r].w = fmaf(xv.x, w0.w, acc[r].w);
                acc[r].x = fmaf(xv.y, w1.x, acc[r].x);
                acc[r].y = fmaf(xv.y, w1.y, acc[r].y);
                acc[r].z = fmaf(xv.y, w1.z, acc[r].z);
                acc[r].w = fmaf(xv.y, w1.w, acc[r].w);
                acc[r].x = fmaf(xv.z, w2.x, acc[r].x);
                acc[r].y = fmaf(xv.z, w2.y, acc[r].y);
                acc[r].z = fmaf(xv.z, w2.z, acc[r].z);
                acc[r].w = fmaf(xv.z, w2.w, acc[r].w);
                acc[r].x = fmaf(xv.w, w3.x, acc[r].x);
                acc[r].y = fmaf(xv.w, w3.y, acc[r].y);
                acc[r].z = fmaf(xv.w, w3.z, acc[r].z);
                acc[r].w = fmaf(xv.w, w3.w, acc[r].w);
            }
        }
        __syncthreads();
    }

    float4 bias = __ldg((const float4*)(b + ng * 4));
#pragma unroll
    for (int r = 0; r < 8; r++) {
        int row = row0 + mg * 8 + r;
        if (row >= NN) break;
        float4 o = acc[r];
        o.x += bias.x; o.y += bias.y; o.z += bias.z; o.w += bias.w;
        uint2 hv;
        *(__half2*)&hv.x = __floats2half2_rn(o.x, o.y);
        *(__half2*)&hv.y = __floats2half2_rn(o.z, o.w);
        *((uint2*)(out + (size_t)row * 64 + ng * 4)) = hv;
    }
}

// ---------------------------------------------------------------------------
// CSR build (unsigned lookback state — R12's signed 2<<30 hit the sign bit).
// ---------------------------------------------------------------------------
__global__ void k_hist(const int* __restrict__ rows, int* __restrict__ cnt,
                       unsigned* __restrict__ state)
{
    if (blockIdx.x == 0 && threadIdx.x < 256) state[threadIdx.x] = 0u;
    int base = blockIdx.x * 1024 + threadIdx.x;
#pragma unroll
    for (int j = 0; j < 4; j++) {
        int e = base + j * 256;
        if (e < EE) atomicAdd(cnt + __ldcs(rows + e), 1);
    }
}

__device__ __forceinline__ int block_scan_excl_512(int v, int* total)
{
    int lane = threadIdx.x & 31, warp = threadIdx.x >> 5;
    int x = v;
#pragma unroll
    for (int d = 1; d < 32; d <<= 1) {
        int y = __shfl_up_sync(0xffffffffu, x, d);
        if (lane >= d) x += y;
    }
    __shared__ int wsum[16];
    if (lane == 31) wsum[warp] = x;
    __syncthreads();
    if (warp == 0) {
        int y = (lane < 16) ? wsum[lane] : 0;
#pragma unroll
        for (int d = 1; d < 16; d <<= 1) {
            int z = __shfl_up_sync(0xffffffffu, y, d);
            if (lane >= d) y += z;
        }
        if (lane < 16) wsum[lane] = y;
    }
    __syncthreads();
    int off = (warp > 0) ? wsum[warp - 1] : 0;
    if (total) *total = wsum[15];
    return x + off - v;   // exclusive
}

__global__ __launch_bounds__(512)
void k_scan_lb(int* __restrict__ cnt, unsigned* __restrict__ state,
               int* __restrict__ rptr, int* __restrict__ cursor)
{
    const int b = blockIdx.x;
    const int i = b * 512 + threadIdx.x;
    int v = (i < NN) ? cnt[i] : 0;
    if (i < NN) cnt[i] = 0;          // ready for next call's k_hist
    int total;
    int ex = block_scan_excl_512(v, &total);

    __shared__ int s_prefix;
    if (threadIdx.x < 32) {
        if (threadIdx.x == 0) {
            unsigned flag = (b == 0) ? 2u : 1u;
            atomicExch(state + b, (flag << 30) | (unsigned)total);
        }
        int prefix = 0;
        if (b > 0) {
            int lane = threadIdx.x;
            for (int j = b - 1; j >= 0; j -= 32) {
                int idx = j - lane;
                unsigned s;
                if (idx >= 0) {
                    do { s = atomicAdd(state + idx, 0u); } while ((s >> 30) == 0u);
                } else {
                    s = (2u << 30);
                }
                unsigned haspre = __ballot_sync(0xffffffffu, (s >> 30) >= 2u);
                int firstpre = __ffs(haspre) - 1;
                int val = (int)(s & 0x3fffffffu);
                int contrib = (firstpre < 0 || lane <= firstpre) ? val : 0;
#pragma unroll
                for (int d = 16; d; d >>= 1)
                    contrib += __shfl_xor_sync(0xffffffffu, contrib, d);
                prefix += contrib;
                if (firstpre >= 0) break;
            }
            if (threadIdx.x == 0)
                atomicExch(state + b, (2u << 30) | (unsigned)(prefix + total));
        }
        if (threadIdx.x == 0) s_prefix = prefix;
    }
    __syncthreads();
    int boff = s_prefix;
    if (i < NN) {
        int p = ex + boff;
        rptr[i]   = p;
        cursor[i] = p;
    }
    if (i == 0) rptr[NN] = EE;
}

__global__ void k_fill(const int* __restrict__ rows, const int* __restrict__ cols,
                       const float* __restrict__ vals,
                       int* __restrict__ cursor, int2* __restrict__ ev)
{
    int base = blockIdx.x * 2048 + threadIdx.x;
#pragma unroll
    for (int j = 0; j < 8; j++) {
        int e = base + j * 256;
        if (e < EE) {
            int r = __ldcs(rows + e);
            int p = atomicAdd(cursor + r, 1);
            ev[p] = make_int2(__ldcs(cols + e), __float_as_int(0.9f * __ldcs(vals + e)));
        }
    }
}

// ---------------------------------------------------------------------------
extern "C" void kernel_launch(void* const* d_in, const int* in_sizes, int n_in,
                              void* d_out, int out_size)
{
    const float* x        = (const float*)d_in[0];
    const int*   adj_rows = (const int*)  d_in[1];
    const int*   adj_cols = (const int*)  d_in[2];
    const float* adj_vals = (const float*)d_in[3];
    const float* fc0_w    = (const float*)d_in[4];
    const float* fc0_b    = (const float*)d_in[5];
    const float* conv_w   = (const float*)d_in[6];
    const float* conv_b   = (const float*)d_in[7];
    const float* fc1_w    = (const float*)d_in[8];
    const float* fc1_b    = (const float*)d_in[9];
    float* out = (float*)d_out;

    __half *h0hp, *xa, *xb;
    int *cntp, *rptrp, *curp;
    unsigned *statep;
    int2 *evp;
    cudaGetSymbolAddress((void**)&h0hp,  g_h0h);
    cudaGetSymbolAddress((void**)&xa,    g_xwhA);
    cudaGetSymbolAddress((void**)&xb,    g_xwhB);
    cudaGetSymbolAddress((void**)&cntp,  g_cnt);
    cudaGetSymbolAddress((void**)&statep,g_state);
    cudaGetSymbolAddress((void**)&rptrp, g_rptr);
    cudaGetSymbolAddress((void**)&curp,  g_cursor);
    cudaGetSymbolAddress((void**)&evp,   g_ev);

    // One-time stream/event handles (resource init, not work caching).
    static cudaStream_t s2 = nullptr;
    static cudaEvent_t  evFork = nullptr, evGemm0 = nullptr;
    if (!s2) {
        cudaStreamCreateWithFlags(&s2, cudaStreamNonBlocking);
        cudaEventCreateWithFlags(&evFork,  cudaEventDisableTiming);
        cudaEventCreateWithFlags(&evGemm0, cudaEventDisableTiming);
    }

    const int GEMM_BLOCKS = (NN + 127) / 128;          // 782
    const int E4_BLOCKS   = (EE + 1023) / 1024;        // 1172 (hist)
    const int E8_BLOCKS   = (EE + 2047) / 2048;        // 586  (fill)

    // ---- fork: dense branch (s2) concurrent with CSR build (main) ----
    cudaEventRecord(evFork, 0);
    cudaStreamWaitEvent(s2, evFork, 0);

    tile_gemm_f32h<NFEAT_K><<<GEMM_BLOCKS, 256, 0, s2>>>(x, fc0_w, fc0_b, h0hp);
    conv_gemm_wmma<<<GEMM_BLOCKS, 256, 0, s2>>>(h0hp, conv_w, xa);
    cudaEventRecord(evGemm0, s2);

    // main: CSR build
    k_hist<<<E4_BLOCKS, 256>>>(adj_rows, cntp, statep);
    k_scan_lb<<<SCAN_BLOCKS, 512>>>(cntp, statep, rptrp, curp);
    k_fill<<<E8_BLOCKS, 256>>>(adj_rows, adj_cols, adj_vals, curp, evp);

    // join
    cudaStreamWaitEvent(0, evGemm0, 0);

    // ---- fused layers: spmm_i + gemm_{i+1}; last one fuses fc1 ----
    layer_fused<<<GEMM_BLOCKS, 256>>>(rptrp, evp, (const __half2*)xa,
                                      (const __half2*)h0hp, conv_b + 0 * NHID,
                                      conv_w + 1 * (size_t)NHID * NHID, xb);
    layer_fused<<<GEMM_BLOCKS, 256>>>(rptrp, evp, (const __half2*)xb,
                                      (const __half2*)h0hp, conv_b + 1 * NHID,
                                      conv_w + 2 * (size_t)NHID * NHID, xa);
    layer_fused<<<GEMM_BLOCKS, 256>>>(rptrp, evp, (const __half2*)xa,
                                      (const __half2*)h0hp, conv_b + 2 * NHID,
                                      conv_w + 3 * (size_t)NHID * NHID, xb);
    layer_last_fused<<<GEMM_BLOCKS, 256>>>(rptrp, evp, (const __half2*)xb,
                                           (const __half2*)h0hp, conv_b + 3 * NHID,
                                           fc1_w, fc1_b, out);
}

// round 15
// speedup vs baseline: 1.1882x; 1.1882x over previous
#include <cuda_runtime.h>
#include <cuda_fp16.h>
#include <mma.h>
#include <cstddef>

using namespace nvcuda;

#define NN      100000
#define EE      1200000
#define NFEAT_K 128
#define NHID    64
#define NCLASS  16
#define NN_PAD  100096   // NN rounded up to 128 (wmma stores unguarded per tile)
#define SCAN_BLOCKS 196  // ceil(NN / 512)

// ---- scratch (__device__ globals; no runtime allocation allowed) ----------
__device__ __half g_h0h [(size_t)NN * NHID];      // h0 = x@fc0_w + fc0_b, fp16
__device__ __half g_xwhA[(size_t)NN_PAD * NHID];  // gemm outputs, ping
__device__ __half g_xwhB[(size_t)NN_PAD * NHID];  // gemm outputs, pong
// CSR (built once per launch; adjacency identical across the 4 layers)
__device__ int      g_cnt  [NN];      // zero at entry (zero-init + re-zeroed by scan)
__device__ unsigned g_state[256];     // lookback state; zeroed by k_hist blk 0
__device__ int      g_rptr [NN + 1];
__device__ int      g_cursor[NN];
__device__ __align__(16) int2 g_ev[EE];           // (col, __float_as_int(0.9*val))

// ---------------------------------------------------------------------------
// SpMM row helper: acc(lane) = 0.1*h0h[r] + cb + sum_e 0.9*val*xwh[col_e]
// (one warp per row, lane owns a half2 -> fully-coalesced 128B gather/edge;
// unroll x8 via int4 ev loads, parity peel for 16B alignment; fp32 accum)
// ---------------------------------------------------------------------------
__device__ __forceinline__ float2 spmm_row(
    int r, int lane, const int* __restrict__ rptr, const int2* __restrict__ ev,
    const __half2* __restrict__ xwh, const __half2* __restrict__ h0h,
    float2 c)
{
    int start = __ldg(rptr + r);
    int end   = __ldg(rptr + r + 1);

    float2 h = __half22float2(__ldg(h0h + (size_t)r * (NHID / 2) + lane));
    float2 acc = make_float2(fmaf(0.1f, h.x, c.x), fmaf(0.1f, h.y, c.y));

    int e = start;
    if ((e & 1) && e < end) {
        int2 e0 = __ldg(ev + e);
        float2 f0 = __half22float2(__ldg(xwh + (size_t)e0.x * (NHID / 2) + lane));
        float v0 = __int_as_float(e0.y);
        acc.x = fmaf(v0, f0.x, acc.x);
        acc.y = fmaf(v0, f0.y, acc.y);
        e++;
    }
    for (; e + 7 < end; e += 8) {
        int4 q0 = __ldg((const int4*)(ev + e) + 0);
        int4 q1 = __ldg((const int4*)(ev + e) + 1);
        int4 q2 = __ldg((const int4*)(ev + e) + 2);
        int4 q3 = __ldg((const int4*)(ev + e) + 3);
        __half2 x0 = __ldg(xwh + (size_t)q0.x * (NHID / 2) + lane);
        __half2 x1 = __ldg(xwh + (size_t)q0.z * (NHID / 2) + lane);
        __half2 x2 = __ldg(xwh + (size_t)q1.x * (NHID / 2) + lane);
        __half2 x3 = __ldg(xwh + (size_t)q1.z * (NHID / 2) + lane);
        __half2 x4 = __ldg(xwh + (size_t)q2.x * (NHID / 2) + lane);
        __half2 x5 = __ldg(xwh + (size_t)q2.z * (NHID / 2) + lane);
        __half2 x6 = __ldg(xwh + (size_t)q3.x * (NHID / 2) + lane);
        __half2 x7 = __ldg(xwh + (size_t)q3.z * (NHID / 2) + lane);
        float2 f0 = __half22float2(x0), f1 = __half22float2(x1);
        float2 f2 = __half22float2(x2), f3 = __half22float2(x3);
        float2 f4 = __half22float2(x4), f5 = __half22float2(x5);
        float2 f6 = __half22float2(x6), f7 = __half22float2(x7);
        float v0 = __int_as_float(q0.y), v1 = __int_as_float(q0.w);
        float v2 = __int_as_float(q1.y), v3 = __int_as_float(q1.w);
        float v4 = __int_as_float(q2.y), v5 = __int_as_float(q2.w);
        float v6 = __int_as_float(q3.y), v7 = __int_as_float(q3.w);
        acc.x = fmaf(v0, f0.x, acc.x);  acc.y = fmaf(v0, f0.y, acc.y);
        acc.x = fmaf(v1, f1.x, acc.x);  acc.y = fmaf(v1, f1.y, acc.y);
        acc.x = fmaf(v2, f2.x, acc.x);  acc.y = fmaf(v2, f2.y, acc.y);
        acc.x = fmaf(v3, f3.x, acc.x);  acc.y = fmaf(v3, f3.y, acc.y);
        acc.x = fmaf(v4, f4.x, acc.x);  acc.y = fmaf(v4, f4.y, acc.y);
        acc.x = fmaf(v5, f5.x, acc.x);  acc.y = fmaf(v5, f5.y, acc.y);
        acc.x = fmaf(v6, f6.x, acc.x);  acc.y = fmaf(v6, f6.y, acc.y);
        acc.x = fmaf(v7, f7.x, acc.x);  acc.y = fmaf(v7, f7.y, acc.y);
    }
    for (; e + 1 < end; e += 2) {
        int4 q = __ldg((const int4*)(ev + e));
        __half2 x0 = __ldg(xwh + (size_t)q.x * (NHID / 2) + lane);
        __half2 x1 = __ldg(xwh + (size_t)q.z * (NHID / 2) + lane);
        float2 f0 = __half22float2(x0), f1 = __half22float2(x1);
        float v0 = __int_as_float(q.y), v1 = __int_as_float(q.w);
        acc.x = fmaf(v0, f0.x, acc.x);  acc.y = fmaf(v0, f0.y, acc.y);
        acc.x = fmaf(v1, f1.x, acc.x);  acc.y = fmaf(v1, f1.y, acc.y);
    }
    if (e < end) {
        int2 e0 = __ldg(ev + e);
        float2 f0 = __half22float2(__ldg(xwh + (size_t)e0.x * (NHID / 2) + lane));
        float v0 = __int_as_float(e0.y);
        acc.x = fmaf(v0, f0.x, acc.x);
        acc.y = fmaf(v0, f0.y, acc.y);
    }
    return acc;
}

// ---------------------------------------------------------------------------
// FUSED layer kernel, 512 threads (16 warps) per 128-row tile:
//   phase 1 (spmm): 16 warps x 8 rows -> relu+fp16 into smem As
//   phase 2 (wmma): 8(M)x2(N) warp grid, warp tile 16x32
// 512 thr/block -> 4 blocks/SM -> 64 warps/SM during spmm (matches the
// unfused spmm concurrency; R14's 256-thr version dropped to ~40 and lost).
// ---------------------------------------------------------------------------
__global__ __launch_bounds__(512)
void layer_fused(const int* __restrict__ rptr, const int2* __restrict__ ev,
                 const __half2* __restrict__ xwh_in,
                 const __half2* __restrict__ h0h, const float* __restrict__ cb,
                 const float* __restrict__ W, __half* __restrict__ xwh_out)
{
    constexpr int LDA = 72;
    __shared__ __half As[128 * LDA];
    __shared__ __half Bs[64 * LDA];

    const int t    = threadIdx.x;
    const int warp = t >> 5;      // 0..15
    const int lane = t & 31;
    const int row0 = blockIdx.x * 128;

    // Stage W[64][64] fp32 -> fp16 smem
#pragma unroll
    for (int i = t; i < 64 * 16; i += 512) {
        int r  = i >> 4;
        int c4 = i & 15;
        float4 v = __ldg((const float4*)(W + (size_t)r * 64) + c4);
        __half2* dst = (__half2*)(Bs + r * LDA + c4 * 4);
        dst[0] = __floats2half2_rn(v.x, v.y);
        dst[1] = __floats2half2_rn(v.z, v.w);
    }

    float2 c = __ldg((const float2*)cb + lane);

    // Phase 1: spmm (16 warps x 8 rows)
#pragma unroll
    for (int rr = warp; rr < 128; rr += 16) {
        int r = row0 + rr;
        float2 acc = make_float2(0.f, 0.f);
        if (r < NN) acc = spmm_row(r, lane, rptr, ev, xwh_in, h0h, c);
        *(__half2*)(As + rr * LDA + lane * 2) =
            __floats2half2_rn(fmaxf(acc.x, 0.f), fmaxf(acc.y, 0.f));
    }
    __syncthreads();

    // Phase 2: wmma 128x64x64, 16 warps as 8(M)x2(N), warp tile 16x32
    const int wm = warp & 7;
    const int wn = warp >> 3;

    wmma::fragment<wmma::accumulator, 16, 16, 16, float> cf[2];
    wmma::fill_fragment(cf[0], 0.f);
    wmma::fill_fragment(cf[1], 0.f);

#pragma unroll
    for (int k = 0; k < 64; k += 16) {
        wmma::fragment<wmma::matrix_a, 16, 16, 16, __half, wmma::row_major> a;
        wmma::fragment<wmma::matrix_b, 16, 16, 16, __half, wmma::row_major> b0, b1;
        wmma::load_matrix_sync(a,  As + (wm * 16) * LDA + k, LDA);
        wmma::load_matrix_sync(b0, Bs + k * LDA + wn * 32 +  0, LDA);
        wmma::load_matrix_sync(b1, Bs + k * LDA + wn * 32 + 16, LDA);
        wmma::mma_sync(cf[0], a, b0, cf[0]);
        wmma::mma_sync(cf[1], a, b1, cf[1]);
    }

#pragma unroll
    for (int j = 0; j < 2; j++) {
        wmma::fragment<wmma::accumulator, 16, 16, 16, __half> hc;
#pragma unroll
        for (int e = 0; e < hc.num_elements; e++)
            hc.x[e] = __float2half(cf[j].x[e]);
        __half* dst = xwh_out + (size_t)(row0 + wm * 16) * 64
                              + wn * 32 + j * 16;
        wmma::store_matrix_sync(dst, hc, 64, wmma::mem_row_major);
    }
}

// ---------------------------------------------------------------------------
// FUSED last layer (512 thr): spmm_3 -> relu -> fc1 (64->16) -> d_out (fp32)
// ---------------------------------------------------------------------------
__global__ __launch_bounds__(512)
void layer_last_fused(const int* __restrict__ rptr, const int2* __restrict__ ev,
                      const __half2* __restrict__ xwh_in,
                      const __half2* __restrict__ h0h, const float* __restrict__ cb,
                      const float* __restrict__ fw, const float* __restrict__ fb,
                      float* __restrict__ out)
{
    constexpr int LDA = 72;
    __shared__ __half As[128 * LDA];
    __shared__ float  Wf[NHID * NCLASS];
    __shared__ float  bf[NCLASS];

    const int t    = threadIdx.x;
    const int warp = t >> 5;
    const int lane = t & 31;
    const int row0 = blockIdx.x * 128;

    for (int i = t; i < NHID * NCLASS; i += 512) Wf[i] = __ldg(fw + i);
    if (t < NCLASS) bf[t] = __ldg(fb + t);

    float2 c = __ldg((const float2*)cb + lane);

#pragma unroll
    for (int rr = warp; rr < 128; rr += 16) {
        int r = row0 + rr;
        float2 acc = make_float2(0.f, 0.f);
        if (r < NN) acc = spmm_row(r, lane, rptr, ev, xwh_in, h0h, c);
        *(__half2*)(As + rr * LDA + lane * 2) =
            __floats2half2_rn(fmaxf(acc.x, 0.f), fmaxf(acc.y, 0.f));
    }
    __syncthreads();

    // fc1: thread t handles row rr = t>>2, cols [4*(t&3), 4*(t&3)+4)
    int rr = t >> 2;
    int j4 = (t & 3) * 4;
    int row = row0 + rr;
    if (row >= NN) return;

    float acc[4];
#pragma unroll
    for (int n = 0; n < 4; n++) acc[n] = bf[j4 + n];

#pragma unroll 8
    for (int k = 0; k < NHID; k++) {
        float xv = __half2float(As[rr * LDA + k]);   // relu already applied
        const float* wr = Wf + k * NCLASS + j4;
#pragma unroll
        for (int n = 0; n < 4; n++) acc[n] = fmaf(xv, wr[n], acc[n]);
    }

    *(float4*)(out + (size_t)row * NCLASS + j4) =
        make_float4(acc[0], acc[1], acc[2], acc[3]);
}

// ---------------------------------------------------------------------------
// Dense-branch kernels (fork): fc0 fp32->fp16, then conv GEMM layer 0 (wmma).
// ---------------------------------------------------------------------------
__global__ __launch_bounds__(256)
void conv_gemm_wmma(const __half* __restrict__ in, const float* __restrict__ W,
                    __half* __restrict__ out)
{
    constexpr int LDA = 72;
    __shared__ __half As[128 * LDA];
    __shared__ __half Bs[64 * LDA];

    const int t    = threadIdx.x;
    const int row0 = blockIdx.x * 128;

#pragma unroll
    for (int i = t; i < 128 * 16; i += 256) {
        int r  = i >> 4;
        int c4 = i & 15;
        int row = row0 + r;
        uint2 u = make_uint2(0u, 0u);
        if (row < NN) u = __ldg((const uint2*)(in + (size_t)row * NHID) + c4);
        __half2 z = __float2half2_rn(0.f);
        __half2* dst = (__half2*)(As + r * LDA + c4 * 4);
        dst[0] = __hmax2(*(__half2*)&u.x, z);
        dst[1] = __hmax2(*(__half2*)&u.y, z);
    }
#pragma unroll
    for (int i = t; i < 64 * 16; i += 256) {
        int r  = i >> 4;
        int c4 = i & 15;
        float4 v = __ldg((const float4*)(W + (size_t)r * 64) + c4);
        __half2* dst = (__half2*)(Bs + r * LDA + c4 * 4);
        dst[0] = __floats2half2_rn(v.x, v.y);
        dst[1] = __floats2half2_rn(v.z, v.w);
    }
    __syncthreads();

    const int wid = t >> 5;
    const int wm  = wid & 3;
    const int wn  = wid >> 2;

    wmma::fragment<wmma::accumulator, 16, 16, 16, float> c[2][2];
#pragma unroll
    for (int i = 0; i < 2; i++)
#pragma unroll
        for (int j = 0; j < 2; j++) wmma::fill_fragment(c[i][j], 0.f);

#pragma unroll
    for (int k = 0; k < 64; k += 16) {
        wmma::fragment<wmma::matrix_a, 16, 16, 16, __half, wmma::row_major> a0, a1;
        wmma::fragment<wmma::matrix_b, 16, 16, 16, __half, wmma::row_major> b0, b1;
        wmma::load_matrix_sync(a0, As + (wm * 32 +  0) * LDA + k, LDA);
        wmma::load_matrix_sync(a1, As + (wm * 32 + 16) * LDA + k, LDA);
        wmma::load_matrix_sync(b0, Bs + k * LDA + wn * 32 +  0, LDA);
        wmma::load_matrix_sync(b1, Bs + k * LDA + wn * 32 + 16, LDA);
        wmma::mma_sync(c[0][0], a0, b0, c[0][0]);
        wmma::mma_sync(c[0][1], a0, b1, c[0][1]);
        wmma::mma_sync(c[1][0], a1, b0, c[1][0]);
        wmma::mma_sync(c[1][1], a1, b1, c[1][1]);
    }

#pragma unroll
    for (int i = 0; i < 2; i++)
#pragma unroll
        for (int j = 0; j < 2; j++) {
            wmma::fragment<wmma::accumulator, 16, 16, 16, __half> hc;
#pragma unroll
            for (int e = 0; e < hc.num_elements; e++)
                hc.x[e] = __float2half(c[i][j].x[e]);
            __half* dst = out + (size_t)(row0 + wm * 32 + i * 16) * 64
                              + wn * 32 + j * 16;
            wmma::store_matrix_sync(dst, hc, 64, wmma::mem_row_major);
        }
}

template<int K>
__global__ __launch_bounds__(256)
void tile_gemm_f32h(const float* __restrict__ in, const float* __restrict__ W,
                    const float* __restrict__ b, __half* __restrict__ out)
{
    constexpr int BM = 128, BN = 64, BK = 64;
    __shared__ float4 xs4[BM][BK / 4];
    __shared__ float4 ws4[BK][BN / 4];

    const int t    = threadIdx.x;
    const int ng   = t & 15;
    const int mg   = t >> 4;
    const int row0 = blockIdx.x * BM;

    float4 acc[8];
#pragma unroll
    for (int r = 0; r < 8; r++) acc[r] = make_float4(0.f, 0.f, 0.f, 0.f);

    for (int kt = 0; kt < K; kt += BK) {
        {
            const float4* Wg = (const float4*)(W + (size_t)kt * BN);
#pragma unroll
            for (int i = t; i < BK * BN / 4; i += 256)
                ws4[i >> 4][i & 15] = __ldg(Wg + i);
        }
#pragma unroll
        for (int i = t; i < BM * BK / 4; i += 256) {
            int r  = i >> 4;
            int k4 = i & 15;
            int row = row0 + r;
            float4 v = make_float4(0.f, 0.f, 0.f, 0.f);
            if (row < NN) v = __ldg((const float4*)(in + (size_t)row * K + kt) + k4);
            xs4[r][k4] = v;
        }
        __syncthreads();

#pragma unroll 4
        for (int k4 = 0; k4 < BK / 4; k4++) {
            float4 w0 = ws4[k4 * 4 + 0][ng];
            float4 w1 = ws4[k4 * 4 + 1][ng];
            float4 w2 = ws4[k4 * 4 + 2][ng];
            float4 w3 = ws4[k4 * 4 + 3][ng];
#pragma unroll
            for (int r = 0; r < 8; r++) {
                float4 xv = xs4[mg * 8 + r][k4];
                acc[r].x = fmaf(xv.x, w0.x, acc[r].x);
                acc[r].y = fmaf(xv.x, w0.y, acc[r].y);
                acc[r].z = fmaf(xv.x, w0.z, acc[r].z);
                acc[r].w = fmaf(xv.x, w0.w, acc[r].w);
                acc[r].x = fmaf(xv.y, w1.x, acc[r].x);
                acc[r].y = fmaf(xv.y, w1.y, acc[r].y);
                acc[r].z = fmaf(xv.y, w1.z, acc[r].z);
                acc[r].w = fmaf(xv.y, w1.w, acc[r].w);
                acc[r].x = fmaf(xv.z, w2.x, acc[r].x);
                acc[r].y = fmaf(xv.z, w2.y, acc[r].y);
                acc[r].z = fmaf(xv.z, w2.z, acc[r].z);
                acc[r].w = fmaf(xv.z, w2.w, acc[r].w);
                acc[r].x = fmaf(xv.w, w3.x, acc[r].x);
                acc[r].y = fmaf(xv.w, w3.y, acc[r].y);
                acc[r].z = fmaf(xv.w, w3.z, acc[r].z);
                acc[r].w = fmaf(xv.w, w3.w, acc[r].w);
            }
        }
        __syncthreads();
    }

    float4 bias = __ldg((const float4*)(b + ng * 4));
#pragma unroll
    for (int r = 0; r < 8; r++) {
        int row = row0 + mg * 8 + r;
        if (row >= NN) break;
        float4 o = acc[r];
        o.x += bias.x; o.y += bias.y; o.z += bias.z; o.w += bias.w;
        uint2 hv;
        *(__half2*)&hv.x = __floats2half2_rn(o.x, o.y);
        *(__half2*)&hv.y = __floats2half2_rn(o.z, o.w);
        *((uint2*)(out + (size_t)row * 64 + ng * 4)) = hv;
    }
}

// ---------------------------------------------------------------------------
// CSR build (unsigned lookback state — signed 2<<30 hit the sign bit in R12).
// ---------------------------------------------------------------------------
__global__ void k_hist(const int* __restrict__ rows, int* __restrict__ cnt,
                       unsigned* __restrict__ state)
{
    if (blockIdx.x == 0 && threadIdx.x < 256) state[threadIdx.x] = 0u;
    int base = blockIdx.x * 1024 + threadIdx.x;
#pragma unroll
    for (int j = 0; j < 4; j++) {
        int e = base + j * 256;
        if (e < EE) atomicAdd(cnt + __ldcs(rows + e), 1);
    }
}

__device__ __forceinline__ int block_scan_excl_512(int v, int* total)
{
    int lane = threadIdx.x & 31, warp = threadIdx.x >> 5;
    int x = v;
#pragma unroll
    for (int d = 1; d < 32; d <<= 1) {
        int y = __shfl_up_sync(0xffffffffu, x, d);
        if (lane >= d) x += y;
    }
    __shared__ int wsum[16];
    if (lane == 31) wsum[warp] = x;
    __syncthreads();
    if (warp == 0) {
        int y = (lane < 16) ? wsum[lane] : 0;
#pragma unroll
        for (int d = 1; d < 16; d <<= 1) {
            int z = __shfl_up_sync(0xffffffffu, y, d);
            if (lane >= d) y += z;
        }
        if (lane < 16) wsum[lane] = y;
    }
    __syncthreads();
    int off = (warp > 0) ? wsum[warp - 1] : 0;
    if (total) *total = wsum[15];
    return x + off - v;   // exclusive
}

__global__ __launch_bounds__(512)
void k_scan_lb(int* __restrict__ cnt, unsigned* __restrict__ state,
               int* __restrict__ rptr, int* __restrict__ cursor)
{
    const int b = blockIdx.x;
    const int i = b * 512 + threadIdx.x;
    int v = (i < NN) ? cnt[i] : 0;
    if (i < NN) cnt[i] = 0;          // ready for next call's k_hist
    int total;
    int ex = block_scan_excl_512(v, &total);

    __shared__ int s_prefix;
    if (threadIdx.x < 32) {
        if (threadIdx.x == 0) {
            unsigned flag = (b == 0) ? 2u : 1u;
            atomicExch(state + b, (flag << 30) | (unsigned)total);
        }
        int prefix = 0;
        if (b > 0) {
            int lane = threadIdx.x;
            for (int j = b - 1; j >= 0; j -= 32) {
                int idx = j - lane;
                unsigned s;
                if (idx >= 0) {
                    do { s = atomicAdd(state + idx, 0u); } while ((s >> 30) == 0u);
                } else {
                    s = (2u << 30);
                }
                unsigned haspre = __ballot_sync(0xffffffffu, (s >> 30) >= 2u);
                int firstpre = __ffs(haspre) - 1;
                int val = (int)(s & 0x3fffffffu);
                int contrib = (firstpre < 0 || lane <= firstpre) ? val : 0;
#pragma unroll
                for (int d = 16; d; d >>= 1)
                    contrib += __shfl_xor_sync(0xffffffffu, contrib, d);
                prefix += contrib;
                if (firstpre >= 0) break;
            }
            if (threadIdx.x == 0)
                atomicExch(state + b, (2u << 30) | (unsigned)(prefix + total));
        }
        if (threadIdx.x == 0) s_prefix = prefix;
    }
    __syncthreads();
    int boff = s_prefix;
    if (i < NN) {
        int p = ex + boff;
        rptr[i]   = p;
        cursor[i] = p;
    }
    if (i == 0) rptr[NN] = EE;
}

__global__ void k_fill(const int* __restrict__ rows, const int* __restrict__ cols,
                       const float* __restrict__ vals,
                       int* __restrict__ cursor, int2* __restrict__ ev)
{
    int base = blockIdx.x * 2048 + threadIdx.x;
#pragma unroll
    for (int j = 0; j < 8; j++) {
        int e = base + j * 256;
        if (e < EE) {
            int r = __ldcs(rows + e);
            int p = atomicAdd(cursor + r, 1);
            ev[p] = make_int2(__ldcs(cols + e), __float_as_int(0.9f * __ldcs(vals + e)));
        }
    }
}

// ---------------------------------------------------------------------------
extern "C" void kernel_launch(void* const* d_in, const int* in_sizes, int n_in,
                              void* d_out, int out_size)
{
    const float* x        = (const float*)d_in[0];
    const int*   adj_rows = (const int*)  d_in[1];
    const int*   adj_cols = (const int*)  d_in[2];
    const float* adj_vals = (const float*)d_in[3];
    const float* fc0_w    = (const float*)d_in[4];
    const float* fc0_b    = (const float*)d_in[5];
    const float* conv_w   = (const float*)d_in[6];
    const float* conv_b   = (const float*)d_in[7];
    const float* fc1_w    = (const float*)d_in[8];
    const float* fc1_b    = (const float*)d_in[9];
    float* out = (float*)d_out;

    __half *h0hp, *xa, *xb;
    int *cntp, *rptrp, *curp;
    unsigned *statep;
    int2 *evp;
    cudaGetSymbolAddress((void**)&h0hp,  g_h0h);
    cudaGetSymbolAddress((void**)&xa,    g_xwhA);
    cudaGetSymbolAddress((void**)&xb,    g_xwhB);
    cudaGetSymbolAddress((void**)&cntp,  g_cnt);
    cudaGetSymbolAddress((void**)&statep,g_state);
    cudaGetSymbolAddress((void**)&rptrp, g_rptr);
    cudaGetSymbolAddress((void**)&curp,  g_cursor);
    cudaGetSymbolAddress((void**)&evp,   g_ev);

    // One-time stream/event handles (resource init, not work caching).
    static cudaStream_t s2 = nullptr;
    static cudaEvent_t  evFork = nullptr, evGemm0 = nullptr;
    if (!s2) {
        cudaStreamCreateWithFlags(&s2, cudaStreamNonBlocking);
        cudaEventCreateWithFlags(&evFork,  cudaEventDisableTiming);
        cudaEventCreateWithFlags(&evGemm0, cudaEventDisableTiming);
    }

    const int GEMM_BLOCKS = (NN + 127) / 128;          // 782
    const int E4_BLOCKS   = (EE + 1023) / 1024;        // 1172 (hist)
    const int E8_BLOCKS   = (EE + 2047) / 2048;        // 586  (fill)

    // ---- fork: dense branch (s2) concurrent with CSR build (main) ----
    cudaEventRecord(evFork, 0);
    cudaStreamWaitEvent(s2, evFork, 0);

    tile_gemm_f32h<NFEAT_K><<<GEMM_BLOCKS, 256, 0, s2>>>(x, fc0_w, fc0_b, h0hp);
    conv_gemm_wmma<<<GEMM_BLOCKS, 256, 0, s2>>>(h0hp, conv_w, xa);
    cudaEventRecord(evGemm0, s2);

    // main: CSR build
    k_hist<<<E4_BLOCKS, 256>>>(adj_rows, cntp, statep);
    k_scan_lb<<<SCAN_BLOCKS, 512>>>(cntp, statep, rptrp, curp);
    k_fill<<<E8_BLOCKS, 256>>>(adj_rows, adj_cols, adj_vals, curp, evp);

    // join
    cudaStreamWaitEvent(0, evGemm0, 0);

    // ---- fused layers (512 thr): spmm_i + gemm_{i+1}; last fuses fc1 ----
    layer_fused<<<GEMM_BLOCKS, 512>>>(rptrp, evp, (const __half2*)xa,
                                      (const __half2*)h0hp, conv_b + 0 * NHID,
                                      conv_w + 1 * (size_t)NHID * NHID, xb);
    layer_fused<<<GEMM_BLOCKS, 512>>>(rptrp, evp, (const __half2*)xb,
                                      (const __half2*)h0hp, conv_b + 1 * NHID,
                                      conv_w + 2 * (size_t)NHID * NHID, xa);
    layer_fused<<<GEMM_BLOCKS, 512>>>(rptrp, evp, (const __half2*)xa,
                                      (const __half2*)h0hp, conv_b + 2 * NHID,
                                      conv_w + 3 * (size_t)NHID * NHID, xb);
    layer_last_fused<<<GEMM_BLOCKS, 512>>>(rptrp, evp, (const __half2*)xb,
                                           (const __half2*)h0hp, conv_b + 3 * NHID,
                                           fc1_w, fc1_b, out);
}

// round 16
// speedup vs baseline: 1.2321x; 1.0370x over previous
#include <cuda_runtime.h>
#include <cuda_fp16.h>
#include <mma.h>
#include <cstddef>

using namespace nvcuda;

#define NN      100000
#define EE      1200000
#define NFEAT_K 128
#define NHID    64
#define NCLASS  16
#define NN_PAD  100096   // NN rounded up to 128 (wmma stores unguarded per tile)
#define SCAN_BLOCKS 196  // ceil(NN / 512)

// ---- scratch (__device__ globals; no runtime allocation allowed) ----------
__device__ __half g_h0h[(size_t)NN * NHID];      // h0 = x@fc0_w + fc0_b, fp16
__device__ __half g_xwh[(size_t)NN_PAD * NHID];  // relu(prev)@conv_w[i], fp16
__device__ __half g_bufA[(size_t)NN * NHID];     // layer outputs (ping), fp16
__device__ __half g_bufB[(size_t)NN * NHID];     // layer outputs (pong), fp16
// CSR (built once per launch; adjacency identical across the 4 layers)
__device__ int      g_cnt  [NN];      // zero at entry (zero-init + re-zeroed by scan)
__device__ unsigned g_state[256];     // lookback state; zeroed by k_hist blk 0
__device__ int      g_rptr [NN + 1];
__device__ int      g_cursor[NN];
__device__ __align__(16) int2 g_ev[EE];          // (col, __float_as_int(0.9*val))

// L2-only gather (random-access stream; L1 allocation is pure overhead here)
__device__ __forceinline__ __half2 ldcg_h2(const __half2* p)
{
    unsigned u;
    asm volatile("ld.global.cg.b32 %0, [%1];" : "=r"(u) : "l"(p));
    return *(__half2*)&u;
}

// ---------------------------------------------------------------------------
// Tensor-core conv GEMM: xwh[r,:] = fp16( relu(in[r,:]) @ W[64,64] )
// Block tile 128x64, 8 warps 4(M)x2(N), warp tile 32x32 wmma m16n16k16.
// ---------------------------------------------------------------------------
__global__ __launch_bounds__(256)
void conv_gemm_wmma(const __half* __restrict__ in, const float* __restrict__ W,
                    __half* __restrict__ out)
{
    constexpr int LDA = 72;
    __shared__ __half As[128 * LDA];
    __shared__ __half Bs[64 * LDA];

    const int t    = threadIdx.x;
    const int row0 = blockIdx.x * 128;

#pragma unroll
    for (int i = t; i < 128 * 16; i += 256) {
        int r  = i >> 4;
        int c4 = i & 15;
        int row = row0 + r;
        uint2 u = make_uint2(0u, 0u);
        if (row < NN) u = __ldg((const uint2*)(in + (size_t)row * NHID) + c4);
        __half2 z = __float2half2_rn(0.f);
        __half2* dst = (__half2*)(As + r * LDA + c4 * 4);
        dst[0] = __hmax2(*(__half2*)&u.x, z);
        dst[1] = __hmax2(*(__half2*)&u.y, z);
    }
#pragma unroll
    for (int i = t; i < 64 * 16; i += 256) {
        int r  = i >> 4;
        int c4 = i & 15;
        float4 v = __ldg((const float4*)(W + (size_t)r * 64) + c4);
        __half2* dst = (__half2*)(Bs + r * LDA + c4 * 4);
        dst[0] = __floats2half2_rn(v.x, v.y);
        dst[1] = __floats2half2_rn(v.z, v.w);
    }
    __syncthreads();

    const int wid = t >> 5;
    const int wm  = wid & 3;
    const int wn  = wid >> 2;

    wmma::fragment<wmma::accumulator, 16, 16, 16, float> c[2][2];
#pragma unroll
    for (int i = 0; i < 2; i++)
#pragma unroll
        for (int j = 0; j < 2; j++) wmma::fill_fragment(c[i][j], 0.f);

#pragma unroll
    for (int k = 0; k < 64; k += 16) {
        wmma::fragment<wmma::matrix_a, 16, 16, 16, __half, wmma::row_major> a0, a1;
        wmma::fragment<wmma::matrix_b, 16, 16, 16, __half, wmma::row_major> b0, b1;
        wmma::load_matrix_sync(a0, As + (wm * 32 +  0) * LDA + k, LDA);
        wmma::load_matrix_sync(a1, As + (wm * 32 + 16) * LDA + k, LDA);
        wmma::load_matrix_sync(b0, Bs + k * LDA + wn * 32 +  0, LDA);
        wmma::load_matrix_sync(b1, Bs + k * LDA + wn * 32 + 16, LDA);
        wmma::mma_sync(c[0][0], a0, b0, c[0][0]);
        wmma::mma_sync(c[0][1], a0, b1, c[0][1]);
        wmma::mma_sync(c[1][0], a1, b0, c[1][0]);
        wmma::mma_sync(c[1][1], a1, b1, c[1][1]);
    }

#pragma unroll
    for (int i = 0; i < 2; i++)
#pragma unroll
        for (int j = 0; j < 2; j++) {
            wmma::fragment<wmma::accumulator, 16, 16, 16, __half> hc;
#pragma unroll
            for (int e = 0; e < hc.num_elements; e++)
                hc.x[e] = __float2half(c[i][j].x[e]);
            __half* dst = out + (size_t)(row0 + wm * 32 + i * 16) * 64
                              + wn * 32 + j * 16;
            wmma::store_matrix_sync(dst, hc, 64, wmma::mem_row_major);
        }
}

// ---------------------------------------------------------------------------
// fp32 register-tiled GEMM (fc0): outh = fp16(in @ W[K,64] + b). Block 128x64x64.
// ---------------------------------------------------------------------------
template<int K>
__global__ __launch_bounds__(256)
void tile_gemm_f32h(const float* __restrict__ in, const float* __restrict__ W,
                    const float* __restrict__ b, __half* __restrict__ out)
{
    constexpr int BM = 128, BN = 64, BK = 64;
    __shared__ float4 xs4[BM][BK / 4];
    __shared__ float4 ws4[BK][BN / 4];

    const int t    = threadIdx.x;
    const int ng   = t & 15;
    const int mg   = t >> 4;
    const int row0 = blockIdx.x * BM;

    float4 acc[8];
#pragma unroll
    for (int r = 0; r < 8; r++) acc[r] = make_float4(0.f, 0.f, 0.f, 0.f);

    for (int kt = 0; kt < K; kt += BK) {
        {
            const float4* Wg = (const float4*)(W + (size_t)kt * BN);
#pragma unroll
            for (int i = t; i < BK * BN / 4; i += 256)
                ws4[i >> 4][i & 15] = __ldg(Wg + i);
        }
#pragma unroll
        for (int i = t; i < BM * BK / 4; i += 256) {
            int r  = i >> 4;
            int k4 = i & 15;
            int row = row0 + r;
            float4 v = make_float4(0.f, 0.f, 0.f, 0.f);
            if (row < NN) v = __ldg((const float4*)(in + (size_t)row * K + kt) + k4);
            xs4[r][k4] = v;
        }
        __syncthreads();

#pragma unroll 4
        for (int k4 = 0; k4 < BK / 4; k4++) {
            float4 w0 = ws4[k4 * 4 + 0][ng];
            float4 w1 = ws4[k4 * 4 + 1][ng];
            float4 w2 = ws4[k4 * 4 + 2][ng];
            float4 w3 = ws4[k4 * 4 + 3][ng];
#pragma unroll
            for (int r = 0; r < 8; r++) {
                float4 xv = xs4[mg * 8 + r][k4];
                acc[r].x = fmaf(xv.x, w0.x, acc[r].x);
                acc[r].y = fmaf(xv.x, w0.y, acc[r].y);
                acc[r].z = fmaf(xv.x, w0.z, acc[r].z);
                acc[r].w = fmaf(xv.x, w0.w, acc[r].w);
                acc[r].x = fmaf(xv.y, w1.x, acc[r].x);
                acc[r].y = fmaf(xv.y, w1.y, acc[r].y);
                acc[r].z = fmaf(xv.y, w1.z, acc[r].z);
                acc[r].w = fmaf(xv.y, w1.w, acc[r].w);
                acc[r].x = fmaf(xv.z, w2.x, acc[r].x);
                acc[r].y = fmaf(xv.z, w2.y, acc[r].y);
                acc[r].z = fmaf(xv.z, w2.z, acc[r].z);
                acc[r].w = fmaf(xv.z, w2.w, acc[r].w);
                acc[r].x = fmaf(xv.w, w3.x, acc[r].x);
                acc[r].y = fmaf(xv.w, w3.y, acc[r].y);
                acc[r].z = fmaf(xv.w, w3.z, acc[r].z);
                acc[r].w = fmaf(xv.w, w3.w, acc[r].w);
            }
        }
        __syncthreads();
    }

    float4 bias = __ldg((const float4*)(b + ng * 4));
#pragma unroll
    for (int r = 0; r < 8; r++) {
        int row = row0 + mg * 8 + r;
        if (row >= NN) break;
        float4 o = acc[r];
        o.x += bias.x; o.y += bias.y; o.z += bias.z; o.w += bias.w;
        uint2 hv;
        *(__half2*)&hv.x = __floats2half2_rn(o.x, o.y);
        *(__half2*)&hv.y = __floats2half2_rn(o.z, o.w);
        *((uint2*)(out + (size_t)row * 64 + ng * 4)) = hv;
    }
}

// ---------------------------------------------------------------------------
// CSR build (unsigned lookback state — R12's signed 2<<30 hit the sign bit).
// ---------------------------------------------------------------------------
__global__ void k_hist(const int* __restrict__ rows, int* __restrict__ cnt,
                       unsigned* __restrict__ state)
{
    if (blockIdx.x == 0 && threadIdx.x < 256) state[threadIdx.x] = 0u;
    int base = blockIdx.x * 1024 + threadIdx.x;
#pragma unroll
    for (int j = 0; j < 4; j++) {
        int e = base + j * 256;
        if (e < EE) atomicAdd(cnt + __ldcs(rows + e), 1);
    }
}

__device__ __forceinline__ int block_scan_excl_512(int v, int* total)
{
    int lane = threadIdx.x & 31, warp = threadIdx.x >> 5;
    int x = v;
#pragma unroll
    for (int d = 1; d < 32; d <<= 1) {
        int y = __shfl_up_sync(0xffffffffu, x, d);
        if (lane >= d) x += y;
    }
    __shared__ int wsum[16];
    if (lane == 31) wsum[warp] = x;
    __syncthreads();
    if (warp == 0) {
        int y = (lane < 16) ? wsum[lane] : 0;
#pragma unroll
        for (int d = 1; d < 16; d <<= 1) {
            int z = __shfl_up_sync(0xffffffffu, y, d);
            if (lane >= d) y += z;
        }
        if (lane < 16) wsum[lane] = y;
    }
    __syncthreads();
    int off = (warp > 0) ? wsum[warp - 1] : 0;
    if (total) *total = wsum[15];
    return x + off - v;   // exclusive
}

__global__ __launch_bounds__(512)
void k_scan_lb(int* __restrict__ cnt, unsigned* __restrict__ state,
               int* __restrict__ rptr, int* __restrict__ cursor)
{
    const int b = blockIdx.x;
    const int i = b * 512 + threadIdx.x;
    int v = (i < NN) ? cnt[i] : 0;
    if (i < NN) cnt[i] = 0;          // ready for next call's k_hist
    int total;
    int ex = block_scan_excl_512(v, &total);

    __shared__ int s_prefix;
    if (threadIdx.x < 32) {
        if (threadIdx.x == 0) {
            unsigned flag = (b == 0) ? 2u : 1u;
            atomicExch(state + b, (flag << 30) | (unsigned)total);
        }
        int prefix = 0;
        if (b > 0) {
            int lane = threadIdx.x;
            for (int j = b - 1; j >= 0; j -= 32) {
                int idx = j - lane;
                unsigned s;
                if (idx >= 0) {
                    do { s = atomicAdd(state + idx, 0u); } while ((s >> 30) == 0u);
                } else {
                    s = (2u << 30);
                }
                unsigned haspre = __ballot_sync(0xffffffffu, (s >> 30) >= 2u);
                int firstpre = __ffs(haspre) - 1;
                int val = (int)(s & 0x3fffffffu);
                int contrib = (firstpre < 0 || lane <= firstpre) ? val : 0;
#pragma unroll
                for (int d = 16; d; d >>= 1)
                    contrib += __shfl_xor_sync(0xffffffffu, contrib, d);
                prefix += contrib;
                if (firstpre >= 0) break;
            }
            if (threadIdx.x == 0)
                atomicExch(state + b, (2u << 30) | (unsigned)(prefix + total));
        }
        if (threadIdx.x == 0) s_prefix = prefix;
    }
    __syncthreads();
    int boff = s_prefix;
    if (i < NN) {
        int p = ex + boff;
        rptr[i]   = p;
        cursor[i] = p;
    }
    if (i == 0) rptr[NN] = EE;
}

__global__ void k_fill(const int* __restrict__ rows, const int* __restrict__ cols,
                       const float* __restrict__ vals,
                       int* __restrict__ cursor, int2* __restrict__ ev)
{
    int base = blockIdx.x * 2048 + threadIdx.x;
#pragma unroll
    for (int j = 0; j < 8; j++) {
        int e = base + j * 256;
        if (e < EE) {
            int r = __ldcs(rows + e);
            int p = atomicAdd(cursor + r, 1);
            ev[p] = make_int2(__ldcs(cols + e), __float_as_int(0.9f * __ldcs(vals + e)));
        }
    }
}

// ---------------------------------------------------------------------------
// SpMM pull (CSR by destination), fp16 gather, fused GCNII epilogue:
//   out[r,:] = fp16( 0.1*h0h[r,:] + cb[:] + sum_e 0.9*val_e * xwh[col_e,:] )
// One warp per row; lane owns a half2 (fully-coalesced 128B gather per edge —
// proven shape; R8's split-warp and R14/15's fusion both regressed).
// Gathers use ld.global.cg (L2-only; random stream has ~0 L1 hit rate).
// Edge loop unroll x8 via int4 ev loads, parity peel. fp32 accum. No atomics.
// ---------------------------------------------------------------------------
__global__ __launch_bounds__(256)
void spmm_pull(const int* __restrict__ rptr, const int2* __restrict__ ev,
               const __half2* __restrict__ xwh, const __half2* __restrict__ h0h,
               const float* __restrict__ cb, __half2* __restrict__ out)
{
    int r    = (blockIdx.x * 256 + threadIdx.x) >> 5;
    int lane = threadIdx.x & 31;
    if (r >= NN) return;

    int start = __ldg(rptr + r);
    int end   = __ldg(rptr + r + 1);

    float2 h = __half22float2(__ldg(h0h + (size_t)r * (NHID / 2) + lane));
    float2 c = __ldg((const float2*)cb + lane);
    float2 acc = make_float2(fmaf(0.1f, h.x, c.x), fmaf(0.1f, h.y, c.y));

    int e = start;
    if ((e & 1) && e < end) {
        int2 e0 = __ldg(ev + e);
        float2 f0 = __half22float2(ldcg_h2(xwh + (size_t)e0.x * (NHID / 2) + lane));
        float v0 = __int_as_float(e0.y);
        acc.x = fmaf(v0, f0.x, acc.x);
        acc.y = fmaf(v0, f0.y, acc.y);
        e++;
    }
    for (; e + 7 < end; e += 8) {
        int4 q0 = __ldg((const int4*)(ev + e) + 0);
        int4 q1 = __ldg((const int4*)(ev + e) + 1);
        int4 q2 = __ldg((const int4*)(ev + e) + 2);
        int4 q3 = __ldg((const int4*)(ev + e) + 3);
        __half2 x0 = ldcg_h2(xwh + (size_t)q0.x * (NHID / 2) + lane);
        __half2 x1 = ldcg_h2(xwh + (size_t)q0.z * (NHID / 2) + lane);
        __half2 x2 = ldcg_h2(xwh + (size_t)q1.x * (NHID / 2) + lane);
        __half2 x3 = ldcg_h2(xwh + (size_t)q1.z * (NHID / 2) + lane);
        __half2 x4 = ldcg_h2(xwh + (size_t)q2.x * (NHID / 2) + lane);
        __half2 x5 = ldcg_h2(xwh + (size_t)q2.z * (NHID / 2) + lane);
        __half2 x6 = ldcg_h2(xwh + (size_t)q3.x * (NHID / 2) + lane);
        __half2 x7 = ldcg_h2(xwh + (size_t)q3.z * (NHID / 2) + lane);
        float2 f0 = __half22float2(x0), f1 = __half22float2(x1);
        float2 f2 = __half22float2(x2), f3 = __half22float2(x3);
        float2 f4 = __half22float2(x4), f5 = __half22float2(x5);
        float2 f6 = __half22float2(x6), f7 = __half22float2(x7);
        float v0 = __int_as_float(q0.y), v1 = __int_as_float(q0.w);
        float v2 = __int_as_float(q1.y), v3 = __int_as_float(q1.w);
        float v4 = __int_as_float(q2.y), v5 = __int_as_float(q2.w);
        float v6 = __int_as_float(q3.y), v7 = __int_as_float(q3.w);
        acc.x = fmaf(v0, f0.x, acc.x);  acc.y = fmaf(v0, f0.y, acc.y);
        acc.x = fmaf(v1, f1.x, acc.x);  acc.y = fmaf(v1, f1.y, acc.y);
        acc.x = fmaf(v2, f2.x, acc.x);  acc.y = fmaf(v2, f2.y, acc.y);
        acc.x = fmaf(v3, f3.x, acc.x);  acc.y = fmaf(v3, f3.y, acc.y);
        acc.x = fmaf(v4, f4.x, acc.x);  acc.y = fmaf(v4, f4.y, acc.y);
        acc.x = fmaf(v5, f5.x, acc.x);  acc.y = fmaf(v5, f5.y, acc.y);
        acc.x = fmaf(v6, f6.x, acc.x);  acc.y = fmaf(v6, f6.y, acc.y);
        acc.x = fmaf(v7, f7.x, acc.x);  acc.y = fmaf(v7, f7.y, acc.y);
    }
    for (; e + 1 < end; e += 2) {
        int4 q = __ldg((const int4*)(ev + e));
        __half2 x0 = ldcg_h2(xwh + (size_t)q.x * (NHID / 2) + lane);
        __half2 x1 = ldcg_h2(xwh + (size_t)q.z * (NHID / 2) + lane);
        float2 f0 = __half22float2(x0), f1 = __half22float2(x1);
        float v0 = __int_as_float(q.y), v1 = __int_as_float(q.w);
        acc.x = fmaf(v0, f0.x, acc.x);  acc.y = fmaf(v0, f0.y, acc.y);
        acc.x = fmaf(v1, f1.x, acc.x);  acc.y = fmaf(v1, f1.y, acc.y);
    }
    if (e < end) {
        int2 e0 = __ldg(ev + e);
        float2 f0 = __half22float2(ldcg_h2(xwh + (size_t)e0.x * (NHID / 2) + lane));
        float v0 = __int_as_float(e0.y);
        acc.x = fmaf(v0, f0.x, acc.x);
        acc.y = fmaf(v0, f0.y, acc.y);
    }

    out[(size_t)r * (NHID / 2) + lane] = __floats2half2_rn(acc.x, acc.y);
}

// ---------------------------------------------------------------------------
// fc1: out[r,:] = relu(in[r,:]) @ W[64,16] + b. One thread per row, fp16 in.
// ---------------------------------------------------------------------------
__global__ __launch_bounds__(256)
void fc1_kernel(const __half* __restrict__ in, const float* __restrict__ W,
                const float* __restrict__ b, float* __restrict__ out)
{
    __shared__ float Ws[NHID * NCLASS];
    __shared__ float bs[NCLASS];
    for (int i = threadIdx.x; i < NHID * NCLASS; i += 256) Ws[i] = W[i];
    if (threadIdx.x < NCLASS) bs[threadIdx.x] = b[threadIdx.x];
    __syncthreads();

    int row = blockIdx.x * 256 + threadIdx.x;
    if (row >= NN) return;

    float4 acc[4];
    const float4* b4 = (const float4*)bs;
#pragma unroll
    for (int n = 0; n < 4; n++) acc[n] = b4[n];

    const uint2* inr = (const uint2*)(in + (size_t)row * NHID);
#pragma unroll 4
    for (int k4 = 0; k4 < NHID / 4; k4++) {
        uint2 u = __ldg(inr + k4);
        float2 lo = __half22float2(*(__half2*)&u.x);
        float2 hi = __half22float2(*(__half2*)&u.y);
        float xs[4] = { fmaxf(lo.x, 0.f), fmaxf(lo.y, 0.f),
                        fmaxf(hi.x, 0.f), fmaxf(hi.y, 0.f) };
#pragma unroll
        for (int kk = 0; kk < 4; kk++) {
            const float4* w4 = (const float4*)(Ws + (size_t)(k4 * 4 + kk) * NCLASS);
#pragma unroll
            for (int n = 0; n < 4; n++) {
                float4 w = w4[n];
                acc[n].x = fmaf(xs[kk], w.x, acc[n].x);
                acc[n].y = fmaf(xs[kk], w.y, acc[n].y);
                acc[n].z = fmaf(xs[kk], w.z, acc[n].z);
                acc[n].w = fmaf(xs[kk], w.w, acc[n].w);
            }
        }
    }

    float4* o = (float4*)(out + (size_t)row * NCLASS);
#pragma unroll
    for (int n = 0; n < 4; n++) o[n] = acc[n];
}

// ---------------------------------------------------------------------------
extern "C" void kernel_launch(void* const* d_in, const int* in_sizes, int n_in,
                              void* d_out, int out_size)
{
    const float* x        = (const float*)d_in[0];
    const int*   adj_rows = (const int*)  d_in[1];
    const int*   adj_cols = (const int*)  d_in[2];
    const float* adj_vals = (const float*)d_in[3];
    const float* fc0_w    = (const float*)d_in[4];
    const float* fc0_b    = (const float*)d_in[5];
    const float* conv_w   = (const float*)d_in[6];
    const float* conv_b   = (const float*)d_in[7];
    const float* fc1_w    = (const float*)d_in[8];
    const float* fc1_b    = (const float*)d_in[9];
    float* out = (float*)d_out;

    __half *h0hp, *xwhp, *ap, *bp;
    int *cntp, *rptrp, *curp;
    unsigned *statep;
    int2 *evp;
    cudaGetSymbolAddress((void**)&h0hp,  g_h0h);
    cudaGetSymbolAddress((void**)&xwhp,  g_xwh);
    cudaGetSymbolAddress((void**)&ap,    g_bufA);
    cudaGetSymbolAddress((void**)&bp,    g_bufB);
    cudaGetSymbolAddress((void**)&cntp,  g_cnt);
    cudaGetSymbolAddress((void**)&statep,g_state);
    cudaGetSymbolAddress((void**)&rptrp, g_rptr);
    cudaGetSymbolAddress((void**)&curp,  g_cursor);
    cudaGetSymbolAddress((void**)&evp,   g_ev);

    // One-time stream/event handles (resource init, not work caching).
    static cudaStream_t s2 = nullptr;
    static cudaEvent_t  evFork = nullptr, evGemm0 = nullptr;
    if (!s2) {
        cudaStreamCreateWithFlags(&s2, cudaStreamNonBlocking);
        cudaEventCreateWithFlags(&evFork,  cudaEventDisableTiming);
        cudaEventCreateWithFlags(&evGemm0, cudaEventDisableTiming);
    }

    const int GEMM_BLOCKS = (NN + 127) / 128;          // 782
    const int E4_BLOCKS   = (EE + 1023) / 1024;        // 1172 (hist)
    const int E8_BLOCKS   = (EE + 2047) / 2048;        // 586  (fill)
    const int SPMM_BLOCKS = (NN + 7) / 8;              // 12500

    // ---- fork: dense branch (s2) concurrent with CSR build (main) ----
    cudaEventRecord(evFork, 0);
    cudaStreamWaitEvent(s2, evFork, 0);

    tile_gemm_f32h<NFEAT_K><<<GEMM_BLOCKS, 256, 0, s2>>>(x, fc0_w, fc0_b, h0hp);
    conv_gemm_wmma<<<GEMM_BLOCKS, 256, 0, s2>>>(h0hp, conv_w, xwhp);
    cudaEventRecord(evGemm0, s2);

    // main: CSR build
    k_hist<<<E4_BLOCKS, 256>>>(adj_rows, cntp, statep);
    k_scan_lb<<<SCAN_BLOCKS, 512>>>(cntp, statep, rptrp, curp);
    k_fill<<<E8_BLOCKS, 256>>>(adj_rows, adj_cols, adj_vals, curp, evp);

    // join: first SpMM needs CSR (main) + xwh/h0h (s2)
    cudaStreamWaitEvent(0, evGemm0, 0);

    // ---- 4 GCNII layers (theta cancels: out = 0.9*A@(relu(li)@W) + 0.1*h0 + b)
    __half* prev = nullptr;
    __half* bufs[2] = { ap, bp };
    for (int i = 0; i < 4; i++) {
        __half* next = bufs[i & 1];
        if (i > 0) {
            conv_gemm_wmma<<<GEMM_BLOCKS, 256>>>(
                prev, conv_w + (size_t)i * NHID * NHID, xwhp);
        }
        spmm_pull<<<SPMM_BLOCKS, 256>>>(rptrp, evp, (const __half2*)xwhp,
                                        (const __half2*)h0hp,
                                        conv_b + (size_t)i * NHID,
                                        (__half2*)next);
        prev = next;
    }

    // ---- fc1: out = relu(prev) @ fc1_w + fc1_b ----
    fc1_kernel<<<(NN + 255) / 256, 256>>>(prev, fc1_w, fc1_b, out);
}